// round 8
// baseline (speedup 1.0000x reference)
#include <cuda_runtime.h>
#include <cstdint>
#include <math.h>

// ---------------------------------------------------------------------------
// Problem constants
// ---------------------------------------------------------------------------
#define BATCH   8
#define DIMC    512
#define SPATIAL 1024             // H*W = 32*32
#define NTOK    (BATCH*SPATIAL)  // 8192 tokens
#define HEADS   8
#define HDIM    64
#define KVLEN   77
#define KVDIM   1024

// ---------------------------------------------------------------------------
// Scratch buffers (static device globals: allocation-free)
// ---------------------------------------------------------------------------
__device__ float g_x   [(size_t)NTOK * DIMC];          // running activation
__device__ float g_t   [(size_t)NTOK * DIMC];          // temp / normalized
__device__ float g_q   [(size_t)NTOK * DIMC];          // cross-attn q
__device__ float g_qkv [(size_t)NTOK * 1536];          // packed self-attn q|k|v
__device__ float g_kv2 [(size_t)(BATCH*KVLEN) * 1024]; // packed cross k|v
__device__ float g_wq  [(size_t)512 * 1536];           // packed qkv weights
__device__ float g_wk2 [(size_t)1024 * 1024];          // packed cross kv weights
__device__ float g_gl  [(size_t)NTOK * 2048];          // geglu a-half / output

// ---------------------------------------------------------------------------
// Warp reduction helpers
// ---------------------------------------------------------------------------
__device__ __forceinline__ float warpSum(float v) {
    #pragma unroll
    for (int o = 16; o > 0; o >>= 1) v += __shfl_xor_sync(0xffffffffu, v, o);
    return v;
}

// ---------------------------------------------------------------------------
// mma / ldmatrix helpers (tf32, raw fp32 bits)
// ---------------------------------------------------------------------------
__device__ __forceinline__ void mma_tf32(float* d, const uint32_t* a, const uint32_t* b) {
    asm volatile(
        "mma.sync.aligned.m16n8k8.row.col.f32.tf32.tf32.f32 "
        "{%0,%1,%2,%3}, {%4,%5,%6,%7}, {%8,%9}, {%0,%1,%2,%3};"
        : "+f"(d[0]), "+f"(d[1]), "+f"(d[2]), "+f"(d[3])
        : "r"(a[0]), "r"(a[1]), "r"(a[2]), "r"(a[3]), "r"(b[0]), "r"(b[1]));
}
__device__ __forceinline__ void ldsm4(uint32_t& r0, uint32_t& r1,
                                      uint32_t& r2, uint32_t& r3, uint32_t addr) {
    asm volatile("ldmatrix.sync.aligned.m8n8.x4.shared.b16 {%0,%1,%2,%3}, [%4];"
                 : "=r"(r0), "=r"(r1), "=r"(r2), "=r"(r3) : "r"(addr));
}
__device__ __forceinline__ void cp_async16(uint32_t dst, const void* src, int bytes) {
    asm volatile("cp.async.cg.shared.global [%0], [%1], 16, %2;\n"
                 :: "r"(dst), "l"(src), "r"(bytes));
}
__device__ __forceinline__ void cp_commit() { asm volatile("cp.async.commit_group;\n"); }
__device__ __forceinline__ void cp_wait1()  { asm volatile("cp.async.wait_group 1;\n"); }
__device__ __forceinline__ void cp_wait0()  { asm volatile("cp.async.wait_group 0;\n"); }

// ---------------------------------------------------------------------------
// GroupNorm + transpose to token-major
// ---------------------------------------------------------------------------
__global__ void groupnorm_kernel(const float* __restrict__ qin,
                                 const float* __restrict__ gamma,
                                 const float* __restrict__ beta,
                                 float* __restrict__ out) {
    const int blk = blockIdx.x;
    const int b = blk >> 5;
    const int grp = blk & 31;
    const float* base = qin + ((size_t)b * DIMC + grp * 16) * SPATIAL;

    float s = 0.f, s2 = 0.f;
    for (int i = threadIdx.x; i < 16 * SPATIAL; i += 256) {
        float v = base[i];
        s += v; s2 += v * v;
    }
    __shared__ float red[2][8];
    s = warpSum(s); s2 = warpSum(s2);
    int wid = threadIdx.x >> 5, lid = threadIdx.x & 31;
    if (lid == 0) { red[0][wid] = s; red[1][wid] = s2; }
    __syncthreads();
    if (wid == 0) {
        float a = (lid < 8) ? red[0][lid] : 0.f;
        float c = (lid < 8) ? red[1][lid] : 0.f;
        a = warpSum(a); c = warpSum(c);
        if (lid == 0) { red[0][0] = a; red[1][0] = c; }
    }
    __syncthreads();
    const float mu  = red[0][0] * (1.f / 16384.f);
    const float var = red[1][0] * (1.f / 16384.f) - mu * mu;
    const float inv = rsqrtf(var + 1e-6f);

    for (int i = threadIdx.x; i < 16 * SPATIAL; i += 256) {
        int c = grp * 16 + (i >> 10);
        int sp = i & 1023;
        float v = (base[i] - mu) * inv * gamma[c] + beta[c];
        out[((size_t)(b * SPATIAL + sp)) * DIMC + c] = v;
    }
}

// ---------------------------------------------------------------------------
// LayerNorm over 512-dim rows. One warp per row.
// ---------------------------------------------------------------------------
__global__ void layernorm_kernel(const float* __restrict__ x,
                                 const float* __restrict__ gamma,
                                 const float* __restrict__ beta,
                                 float* __restrict__ out, int rows) {
    int row = blockIdx.x * 8 + (threadIdx.x >> 5);
    if (row >= rows) return;
    int lid = threadIdx.x & 31;
    const float4* xr = (const float4*)(x + (size_t)row * DIMC);

    float4 vals[4];
    float s = 0.f, s2 = 0.f;
    #pragma unroll
    for (int i = 0; i < 4; i++) {
        float4 v = xr[lid + 32 * i];
        vals[i] = v;
        s  += v.x + v.y + v.z + v.w;
        s2 += v.x*v.x + v.y*v.y + v.z*v.z + v.w*v.w;
    }
    s = warpSum(s); s2 = warpSum(s2);
    const float mu  = s * (1.f / 512.f);
    const float inv = rsqrtf(s2 * (1.f / 512.f) - mu * mu + 1e-5f);

    float4* orow = (float4*)(out + (size_t)row * DIMC);
    const float4* g4 = (const float4*)gamma;
    const float4* b4 = (const float4*)beta;
    #pragma unroll
    for (int i = 0; i < 4; i++) {
        int idx = lid + 32 * i;
        float4 v = vals[i], g = g4[idx], b = b4[idx], o;
        o.x = (v.x - mu) * inv * g.x + b.x;
        o.y = (v.y - mu) * inv * g.y + b.y;
        o.z = (v.z - mu) * inv * g.z + b.z;
        o.w = (v.w - mu) * inv * g.w + b.w;
        orow[idx] = o;
    }
}

// ---------------------------------------------------------------------------
// Weight packing
// ---------------------------------------------------------------------------
__global__ void pack3_kernel(const float* __restrict__ w0,
                             const float* __restrict__ w1,
                             const float* __restrict__ w2,
                             float* __restrict__ out) {
    int i = blockIdx.x * 256 + threadIdx.x;
    if (i >= 512 * 1536 / 4) return;
    int row = i / 384;
    int c4  = i % 384;
    const float4* src;
    int cc = c4;
    if (c4 < 128)       { src = (const float4*)w0; }
    else if (c4 < 256)  { src = (const float4*)w1; cc = c4 - 128; }
    else                { src = (const float4*)w2; cc = c4 - 256; }
    ((float4*)out)[i] = src[row * 128 + cc];
}

__global__ void pack2_kernel(const float* __restrict__ w0,
                             const float* __restrict__ w1,
                             float* __restrict__ out) {
    int i = blockIdx.x * 256 + threadIdx.x;
    if (i >= 1024 * 1024 / 4) return;
    int row = i / 256;
    int c4  = i % 256;
    const float4* src = c4 < 128 ? (const float4*)w0 : (const float4*)w1;
    int cc = c4 < 128 ? c4 : c4 - 128;
    ((float4*)out)[i] = src[row * 128 + cc];
}

// ---------------------------------------------------------------------------
// Final transpose + residual
// ---------------------------------------------------------------------------
__global__ void output_kernel(const float* __restrict__ t,
                              const float* __restrict__ qin,
                              float* __restrict__ out) {
    int i = blockIdx.x * 256 + threadIdx.x;
    if (i >= BATCH * DIMC * SPATIAL) return;
    int sp = i & 1023;
    int bc = i >> 10;
    int c = bc & 511;
    int b = bc >> 9;
    out[i] = t[((size_t)(b * SPATIAL + sp)) * DIMC + c] + qin[i];
}

// ===========================================================================
// Fused flash self-attention (ldmatrix fragment loads).
// ===========================================================================
#define FSTR 68
#define PSTR 132
#define FS_SQ   0
#define FS_SK   (128*FSTR)
#define FS_SVT  (FS_SK + 128*FSTR)
#define FS_SP   (FS_SVT + 64*PSTR)
#define FS_TOTAL (FS_SP + 128*PSTR)

__global__ void __launch_bounds__(256) flash_self_kernel(
    const float* __restrict__ qkv, float* __restrict__ outp) {
    extern __shared__ float sm[];
    float* sQ  = sm + FS_SQ;
    float* sK  = sm + FS_SK;
    float* sVt = sm + FS_SVT;
    float* sP  = sm + FS_SP;

    const int b  = blockIdx.y >> 3;
    const int h  = blockIdx.y & 7;
    const int q0 = blockIdx.x * 128;
    const int tid = threadIdx.x;
    const int warp = tid >> 5;
    const int lane = tid & 31;
    const int g  = lane >> 2;
    const int tg = lane & 3;
    const int wm = warp * 16;

    const uint32_t smb = (uint32_t)__cvta_generic_to_shared(sm);
    const uint32_t lmrow = (lane & 15);
    const uint32_t lmhi  = (lane >> 4) << 2;

    for (int i = tid; i < 2048; i += 256) {
        int row = i >> 4;
        int c4  = (i & 15) * 4;
        const float4 v = *(const float4*)(qkv +
            (size_t)(b * 1024 + q0 + row) * 1536 + h * 64 + c4);
        float* d = sQ + row * FSTR + c4;
        d[0] = v.x * 0.125f; d[1] = v.y * 0.125f;
        d[2] = v.z * 0.125f; d[3] = v.w * 0.125f;
    }
    __syncthreads();

    uint32_t qf[8][4];
    {
        const uint32_t qbase = smb + (FS_SQ + (wm + lmrow) * FSTR + lmhi) * 4;
        #pragma unroll
        for (int kc = 0; kc < 8; kc++)
            ldsm4(qf[kc][0], qf[kc][1], qf[kc][2], qf[kc][3], qbase + kc * 32);
    }

    float m_[2] = {-1e30f, -1e30f};
    float l_[2] = {0.f, 0.f};
    float acco[8][4];
    #pragma unroll
    for (int i = 0; i < 8; i++)
        #pragma unroll
        for (int r = 0; r < 4; r++) acco[i][r] = 0.f;

    const uint32_t kbase = smb + (FS_SK + lmrow * FSTR + lmhi) * 4;
    const uint32_t pbase = smb + (FS_SP + (wm + lmrow) * PSTR + lmhi) * 4;
    const uint32_t vbase = smb + (FS_SVT + lmrow * PSTR + lmhi) * 4;

    for (int j = 0; j < 8; j++) {
        for (int i = tid; i < 2048; i += 256) {
            int row = i >> 4;
            int c4  = (i & 15) * 4;
            const float* base = qkv + (size_t)(b * 1024 + j * 128 + row) * 1536 + h * 64;
            const float4 kv4 = *(const float4*)(base + 512 + c4);
            float* dk = sK + row * FSTR + c4;
            dk[0] = kv4.x; dk[1] = kv4.y; dk[2] = kv4.z; dk[3] = kv4.w;
            const float4 vv = *(const float4*)(base + 1024 + c4);
            sVt[(c4 + 0) * PSTR + row] = vv.x;
            sVt[(c4 + 1) * PSTR + row] = vv.y;
            sVt[(c4 + 2) * PSTR + row] = vv.z;
            sVt[(c4 + 3) * PSTR + row] = vv.w;
        }
        __syncthreads();

        float accs[16][4];
        #pragma unroll
        for (int nt = 0; nt < 16; nt++)
            #pragma unroll
            for (int r = 0; r < 4; r++) accs[nt][r] = 0.f;

        #pragma unroll
        for (int kc = 0; kc < 8; kc++) {
            const uint32_t ka = kbase + kc * 32;
            #pragma unroll
            for (int p = 0; p < 8; p++) {
                uint32_t b0, b1, b2, b3;
                ldsm4(b0, b1, b2, b3, ka + (uint32_t)(p * 16 * FSTR) * 4);
                uint32_t bf0[2] = {b0, b2};
                uint32_t bf1[2] = {b1, b3};
                mma_tf32(accs[2 * p],     qf[kc], bf0);
                mma_tf32(accs[2 * p + 1], qf[kc], bf1);
            }
        }

        float mx0 = -1e30f, mx1 = -1e30f;
        #pragma unroll
        for (int nt = 0; nt < 16; nt++) {
            mx0 = fmaxf(mx0, fmaxf(accs[nt][0], accs[nt][1]));
            mx1 = fmaxf(mx1, fmaxf(accs[nt][2], accs[nt][3]));
        }
        mx0 = fmaxf(mx0, __shfl_xor_sync(0xffffffffu, mx0, 1));
        mx0 = fmaxf(mx0, __shfl_xor_sync(0xffffffffu, mx0, 2));
        mx1 = fmaxf(mx1, __shfl_xor_sync(0xffffffffu, mx1, 1));
        mx1 = fmaxf(mx1, __shfl_xor_sync(0xffffffffu, mx1, 2));
        const float mn0 = fmaxf(m_[0], mx0);
        const float mn1 = fmaxf(m_[1], mx1);
        const float c0 = __expf(m_[0] - mn0);
        const float c1 = __expf(m_[1] - mn1);
        l_[0] *= c0; l_[1] *= c1;
        #pragma unroll
        for (int nt = 0; nt < 8; nt++) {
            acco[nt][0] *= c0; acco[nt][1] *= c0;
            acco[nt][2] *= c1; acco[nt][3] *= c1;
        }
        float rs0 = 0.f, rs1 = 0.f;
        float* p0 = sP + (wm + g) * PSTR + 2 * tg;
        float* p1 = sP + (wm + g + 8) * PSTR + 2 * tg;
        #pragma unroll
        for (int nt = 0; nt < 16; nt++) {
            const float e0 = __expf(accs[nt][0] - mn0);
            const float e1 = __expf(accs[nt][1] - mn0);
            const float e2 = __expf(accs[nt][2] - mn1);
            const float e3 = __expf(accs[nt][3] - mn1);
            rs0 += e0 + e1; rs1 += e2 + e3;
            p0[nt * 8 + 0] = e0; p0[nt * 8 + 1] = e1;
            p1[nt * 8 + 0] = e2; p1[nt * 8 + 1] = e3;
        }
        rs0 += __shfl_xor_sync(0xffffffffu, rs0, 1);
        rs0 += __shfl_xor_sync(0xffffffffu, rs0, 2);
        rs1 += __shfl_xor_sync(0xffffffffu, rs1, 1);
        rs1 += __shfl_xor_sync(0xffffffffu, rs1, 2);
        l_[0] += rs0; l_[1] += rs1;
        m_[0] = mn0; m_[1] = mn1;
        __syncwarp();

        #pragma unroll
        for (int kc = 0; kc < 16; kc++) {
            uint32_t af[4];
            ldsm4(af[0], af[1], af[2], af[3], pbase + kc * 32);
            const uint32_t va = vbase + kc * 32;
            #pragma unroll
            for (int p = 0; p < 4; p++) {
                uint32_t b0, b1, b2, b3;
                ldsm4(b0, b1, b2, b3, va + (uint32_t)(p * 16 * PSTR) * 4);
                uint32_t bf0[2] = {b0, b2};
                uint32_t bf1[2] = {b1, b3};
                mma_tf32(acco[2 * p],     af, bf0);
                mma_tf32(acco[2 * p + 1], af, bf1);
            }
        }
        __syncthreads();   // before overwriting sK/sVt next iter
    }

    const float i0 = 1.f / l_[0];
    const float i1 = 1.f / l_[1];
    const int row0 = b * 1024 + q0 + wm + g;
    #pragma unroll
    for (int nt = 0; nt < 8; nt++) {
        const int col = h * 64 + nt * 8 + 2 * tg;
        outp[(size_t)row0 * 512 + col]           = acco[nt][0] * i0;
        outp[(size_t)row0 * 512 + col + 1]       = acco[nt][1] * i0;
        outp[(size_t)(row0 + 8) * 512 + col]     = acco[nt][2] * i1;
        outp[(size_t)(row0 + 8) * 512 + col + 1] = acco[nt][3] * i1;
    }
}

// ===========================================================================
// Fused flash cross-attention (kv len 77, padded to 80, single tile).
// ===========================================================================
#define CSTR 84
#define CF_SQ   0
#define CF_SK   (128*FSTR)
#define CF_SVT  (CF_SK + 80*FSTR)
#define CF_SP   (CF_SVT + 64*CSTR)
#define CF_TOTAL (CF_SP + 128*CSTR)

__global__ void __launch_bounds__(256) flash_cross_kernel(
    const float* __restrict__ qsrc, const float* __restrict__ kv2,
    float* __restrict__ outp) {
    extern __shared__ float sm[];
    float* sQ  = sm + CF_SQ;
    float* sK  = sm + CF_SK;
    float* sVt = sm + CF_SVT;
    float* sP  = sm + CF_SP;

    const int b  = blockIdx.y >> 3;
    const int h  = blockIdx.y & 7;
    const int q0 = blockIdx.x * 128;
    const int tid = threadIdx.x;
    const int warp = tid >> 5;
    const int lane = tid & 31;
    const int g  = lane >> 2;
    const int tg = lane & 3;
    const int wm = warp * 16;

    const uint32_t smb = (uint32_t)__cvta_generic_to_shared(sm);
    const uint32_t lmrow = (lane & 15);
    const uint32_t lmhi  = (lane >> 4) << 2;

    for (int i = tid; i < 2048; i += 256) {
        int row = i >> 4;
        int c4  = (i & 15) * 4;
        const float4 v = *(const float4*)(qsrc +
            (size_t)(b * 1024 + q0 + row) * 512 + h * 64 + c4);
        float* d = sQ + row * FSTR + c4;
        d[0] = v.x * 0.125f; d[1] = v.y * 0.125f;
        d[2] = v.z * 0.125f; d[3] = v.w * 0.125f;
    }
    for (int i = tid; i < 1280; i += 256) {
        int row = i >> 4;
        int c4  = (i & 15) * 4;
        float4 kk = make_float4(0.f, 0.f, 0.f, 0.f);
        float4 vv = make_float4(0.f, 0.f, 0.f, 0.f);
        if (row < KVLEN) {
            const float* base = kv2 + (size_t)(b * KVLEN + row) * 1024 + h * 64;
            kk = *(const float4*)(base + c4);
            vv = *(const float4*)(base + 512 + c4);
        }
        float* dk = sK + row * FSTR + c4;
        dk[0] = kk.x; dk[1] = kk.y; dk[2] = kk.z; dk[3] = kk.w;
        sVt[(c4 + 0) * CSTR + row] = vv.x;
        sVt[(c4 + 1) * CSTR + row] = vv.y;
        sVt[(c4 + 2) * CSTR + row] = vv.z;
        sVt[(c4 + 3) * CSTR + row] = vv.w;
    }
    __syncthreads();

    uint32_t qf[8][4];
    {
        const uint32_t qbase = smb + (CF_SQ + (wm + lmrow) * FSTR + lmhi) * 4;
        #pragma unroll
        for (int kc = 0; kc < 8; kc++)
            ldsm4(qf[kc][0], qf[kc][1], qf[kc][2], qf[kc][3], qbase + kc * 32);
    }

    float accs[10][4];
    #pragma unroll
    for (int nt = 0; nt < 10; nt++)
        #pragma unroll
        for (int r = 0; r < 4; r++) accs[nt][r] = 0.f;
    {
        const uint32_t kbase = smb + (CF_SK + lmrow * FSTR + lmhi) * 4;
        #pragma unroll
        for (int kc = 0; kc < 8; kc++) {
            const uint32_t ka = kbase + kc * 32;
            #pragma unroll
            for (int p = 0; p < 5; p++) {
                uint32_t b0, b1, b2, b3;
                ldsm4(b0, b1, b2, b3, ka + (uint32_t)(p * 16 * FSTR) * 4);
                uint32_t bf0[2] = {b0, b2};
                uint32_t bf1[2] = {b1, b3};
                mma_tf32(accs[2 * p],     qf[kc], bf0);
                mma_tf32(accs[2 * p + 1], qf[kc], bf1);
            }
        }
    }

    #pragma unroll
    for (int nt = 0; nt < 10; nt++) {
        const int col0 = nt * 8 + 2 * tg;
        if (col0 >= KVLEN)     { accs[nt][0] = -1e30f; accs[nt][2] = -1e30f; }
        if (col0 + 1 >= KVLEN) { accs[nt][1] = -1e30f; accs[nt][3] = -1e30f; }
    }
    float mx0 = -1e30f, mx1 = -1e30f;
    #pragma unroll
    for (int nt = 0; nt < 10; nt++) {
        mx0 = fmaxf(mx0, fmaxf(accs[nt][0], accs[nt][1]));
        mx1 = fmaxf(mx1, fmaxf(accs[nt][2], accs[nt][3]));
    }
    mx0 = fmaxf(mx0, __shfl_xor_sync(0xffffffffu, mx0, 1));
    mx0 = fmaxf(mx0, __shfl_xor_sync(0xffffffffu, mx0, 2));
    mx1 = fmaxf(mx1, __shfl_xor_sync(0xffffffffu, mx1, 1));
    mx1 = fmaxf(mx1, __shfl_xor_sync(0xffffffffu, mx1, 2));

    float rs0 = 0.f, rs1 = 0.f;
    float* p0 = sP + (wm + g) * CSTR + 2 * tg;
    float* p1 = sP + (wm + g + 8) * CSTR + 2 * tg;
    #pragma unroll
    for (int nt = 0; nt < 10; nt++) {
        const float e0 = __expf(accs[nt][0] - mx0);
        const float e1 = __expf(accs[nt][1] - mx0);
        const float e2 = __expf(accs[nt][2] - mx1);
        const float e3 = __expf(accs[nt][3] - mx1);
        rs0 += e0 + e1; rs1 += e2 + e3;
        p0[nt * 8 + 0] = e0; p0[nt * 8 + 1] = e1;
        p1[nt * 8 + 0] = e2; p1[nt * 8 + 1] = e3;
    }
    rs0 += __shfl_xor_sync(0xffffffffu, rs0, 1);
    rs0 += __shfl_xor_sync(0xffffffffu, rs0, 2);
    rs1 += __shfl_xor_sync(0xffffffffu, rs1, 1);
    rs1 += __shfl_xor_sync(0xffffffffu, rs1, 2);
    __syncwarp();

    float acco[8][4];
    #pragma unroll
    for (int nt = 0; nt < 8; nt++)
        #pragma unroll
        for (int r = 0; r < 4; r++) acco[nt][r] = 0.f;
    {
        const uint32_t pb = smb + (CF_SP + (wm + lmrow) * CSTR + lmhi) * 4;
        const uint32_t vb = smb + (CF_SVT + lmrow * CSTR + lmhi) * 4;
        #pragma unroll
        for (int kc = 0; kc < 10; kc++) {
            uint32_t af[4];
            ldsm4(af[0], af[1], af[2], af[3], pb + kc * 32);
            const uint32_t va = vb + kc * 32;
            #pragma unroll
            for (int p = 0; p < 4; p++) {
                uint32_t b0, b1, b2, b3;
                ldsm4(b0, b1, b2, b3, va + (uint32_t)(p * 16 * CSTR) * 4);
                uint32_t bf0[2] = {b0, b2};
                uint32_t bf1[2] = {b1, b3};
                mma_tf32(acco[2 * p],     af, bf0);
                mma_tf32(acco[2 * p + 1], af, bf1);
            }
        }
    }

    const float i0 = 1.f / rs0;
    const float i1 = 1.f / rs1;
    const int row0 = b * 1024 + q0 + wm + g;
    #pragma unroll
    for (int nt = 0; nt < 8; nt++) {
        const int col = h * 64 + nt * 8 + 2 * tg;
        outp[(size_t)row0 * 512 + col]           = acco[nt][0] * i0;
        outp[(size_t)row0 * 512 + col + 1]       = acco[nt][1] * i0;
        outp[(size_t)(row0 + 8) * 512 + col]     = acco[nt][2] * i1;
        outp[(size_t)(row0 + 8) * 512 + col + 1] = acco[nt][3] * i1;
    }
}

// ===========================================================================
// TF32 tensor-core GEMM, specialized: C = A@B (+bias)(+Res / GEGLU)
//   A [M,K] row-major, B [K,N] row-major. N % 128 == 0, K % 32 == 0.
//   Only M may be ragged (kv2: 616). 2-stage cp.async double buffer
//   (71.7KB smem -> 2 CTAs/SM), ldmatrix A-fragments.
// ===========================================================================
#define BM 128
#define BN 128
#define BK 32
#define ASTRIDE 36
#define BSTRIDE 136
#define STG_A (128*ASTRIDE)              // 4608 floats
#define STG_FLOATS (STG_A + 32*BSTRIDE)  // 8960 floats
#define GEMM_SMEM (2 * STG_FLOATS * 4)   // 71680 B -> 2 CTAs/SM

__global__ void __launch_bounds__(256, 2) gemm_tf32_kernel(
    const float* __restrict__ A, int lda,
    const float* __restrict__ B, int ldb,
    float* __restrict__ C, int ldc,
    const float* __restrict__ Res, int ldres,
    const float* __restrict__ bias,
    int M, int N, int K, int emode) {

    extern __shared__ float smem[];

    const int m0 = blockIdx.y * BM;
    const int n0 = blockIdx.x * BN;
    const int tid = threadIdx.x;
    const int warp = tid >> 5;
    const int lane = tid & 31;
    const int g  = lane >> 2;
    const int tg = lane & 3;
    const int wm = (warp >> 2) * 64;
    const int wn = (warp & 3) * 32;

    const uint32_t smem_u32 = (uint32_t)__cvta_generic_to_shared(smem);
    const int nk = K / BK;

    float acc[4][4][4];
    #pragma unroll
    for (int i = 0; i < 4; i++)
        #pragma unroll
        for (int j = 0; j < 4; j++)
            #pragma unroll
            for (int r = 0; r < 4; r++) acc[i][j][r] = 0.f;

    auto load_stage = [&](int stage, int k0) {
        const uint32_t abase = smem_u32 + (uint32_t)(stage * STG_FLOATS) * 4;
        #pragma unroll
        for (int i = 0; i < 4; i++) {
            int idx = tid + i * 256;
            int row = idx >> 3;
            int kc  = (idx & 7) * 4;
            int bytes = (m0 + row < M) ? 16 : 0;
            cp_async16(abase + (uint32_t)(row * ASTRIDE + kc) * 4,
                       A + (long long)(m0 + row) * lda + k0 + kc, bytes);
        }
        const uint32_t bbase = abase + (uint32_t)STG_A * 4;
        #pragma unroll
        for (int i = 0; i < 4; i++) {
            int idx = tid + i * 256;
            int k  = idx >> 5;
            int nc = (idx & 31) * 4;
            cp_async16(bbase + (uint32_t)(k * BSTRIDE + nc) * 4,
                       B + (long long)(k0 + k) * ldb + n0 + nc, 16);
        }
        cp_commit();
    };

    const uint32_t a_lm = smem_u32 +
        (uint32_t)((wm + (lane & 15)) * ASTRIDE + ((lane >> 4) << 2)) * 4;

    auto compute_stage = [&](int stage) {
        const uint32_t abase = a_lm + (uint32_t)(stage * STG_FLOATS) * 4;
        const uint32_t* Bs = (const uint32_t*)(smem + stage * STG_FLOATS + STG_A);
        #pragma unroll
        for (int ks = 0; ks < 4; ks++) {
            const int kk = ks * 8;
            uint32_t afr[4][4];
            #pragma unroll
            for (int mt = 0; mt < 4; mt++)
                ldsm4(afr[mt][0], afr[mt][1], afr[mt][2], afr[mt][3],
                      abase + (uint32_t)(mt * 16 * ASTRIDE + kk) * 4);
            uint32_t bfr[4][2];
            #pragma unroll
            for (int nt = 0; nt < 4; nt++) {
                const int nb = wn + nt * 8;
                bfr[nt][0] = Bs[(kk + tg)     * BSTRIDE + nb + g];
                bfr[nt][1] = Bs[(kk + tg + 4) * BSTRIDE + nb + g];
            }
            #pragma unroll
            for (int mt = 0; mt < 4; mt++)
                #pragma unroll
                for (int nt = 0; nt < 4; nt++)
                    mma_tf32(acc[mt][nt], afr[mt], bfr[nt]);
        }
    };

    load_stage(0, 0);
    if (nk > 1) load_stage(1, BK);
    for (int kt = 0; kt < nk; kt++) {
        if (kt + 1 < nk) cp_wait1(); else cp_wait0();
        __syncthreads();
        compute_stage(kt & 1);
        __syncthreads();
        if (kt + 2 < nk) load_stage(kt & 1, (kt + 2) * BK);
    }

    // ---- epilogue ----
    #pragma unroll
    for (int mt = 0; mt < 4; mt++) {
        #pragma unroll
        for (int nt = 0; nt < 4; nt++) {
            const int row0 = m0 + wm + mt * 16 + g;
            const int col0 = n0 + wn + nt * 8 + tg * 2;
            #pragma unroll
            for (int r = 0; r < 4; r++) {
                const int row = row0 + (r >> 1) * 8;
                const int col = col0 + (r & 1);
                if (row < M) {
                    float v = acc[mt][nt][r];
                    if (bias) v += bias[col];
                    if (emode == 1) {
                        float ge = 0.5f * v * (1.f + erff(v * 0.70710678118654752f));
                        v = Res[(long long)row * ldres + col] * ge;
                    } else if (Res) {
                        v += Res[(long long)row * ldres + col];
                    }
                    C[(long long)row * ldc + col] = v;
                }
            }
        }
    }
}

// ---------------------------------------------------------------------------
// Host side
// ---------------------------------------------------------------------------
static void gemm(const float* A, int lda, const float* B, int ldb,
                 float* C, int ldc, const float* Res, int ldres,
                 const float* bias, int M, int N, int K, int emode = 0) {
    dim3 grid(N / BN, (M + BM - 1) / BM);
    gemm_tf32_kernel<<<grid, 256, GEMM_SMEM>>>(
        A, lda, B, ldb, C, ldc, Res, ldres, bias, M, N, K, emode);
}

extern "C" void kernel_launch(void* const* d_in, const int* in_sizes, int n_in,
                              void* d_out, int out_size) {
    const float* in_q     = (const float*)d_in[0];
    const float* in_kv    = (const float*)d_in[1];
    const float* gn_g     = (const float*)d_in[2];
    const float* gn_b     = (const float*)d_in[3];
    const float* ln2_g    = (const float*)d_in[4];
    const float* ln2_b    = (const float*)d_in[5];
    const float* ln3_g    = (const float*)d_in[6];
    const float* ln3_b    = (const float*)d_in[7];
    const float* ln4_g    = (const float*)d_in[8];
    const float* ln4_b    = (const float*)d_in[9];
    const float* fc_in_w  = (const float*)d_in[10];
    const float* fc_in_b  = (const float*)d_in[11];
    const float* fc_out_w = (const float*)d_in[12];
    const float* fc_out_b = (const float*)d_in[13];
    const float* a1_q     = (const float*)d_in[14];
    const float* a1_k     = (const float*)d_in[15];
    const float* a1_v     = (const float*)d_in[16];
    const float* a1_o     = (const float*)d_in[17];
    const float* a1_ob    = (const float*)d_in[18];
    const float* a2_q     = (const float*)d_in[19];
    const float* a2_k     = (const float*)d_in[20];
    const float* a2_v     = (const float*)d_in[21];
    const float* a2_o     = (const float*)d_in[22];
    const float* a2_ob    = (const float*)d_in[23];
    const float* ff_proj_w = (const float*)d_in[24];
    const float* ff_proj_b = (const float*)d_in[25];
    const float* ff_out_w  = (const float*)d_in[26];
    const float* ff_out_b  = (const float*)d_in[27];

    cudaFuncSetAttribute(gemm_tf32_kernel,
                         cudaFuncAttributeMaxDynamicSharedMemorySize, GEMM_SMEM);
    cudaFuncSetAttribute(flash_self_kernel,
                         cudaFuncAttributeMaxDynamicSharedMemorySize, FS_TOTAL * 4);
    cudaFuncSetAttribute(flash_cross_kernel,
                         cudaFuncAttributeMaxDynamicSharedMemorySize, CF_TOTAL * 4);

    float *x, *t, *q, *qkv, *kv2, *wq, *wk2, *gl;
    cudaGetSymbolAddress((void**)&x,   g_x);
    cudaGetSymbolAddress((void**)&t,   g_t);
    cudaGetSymbolAddress((void**)&q,   g_q);
    cudaGetSymbolAddress((void**)&qkv, g_qkv);
    cudaGetSymbolAddress((void**)&kv2, g_kv2);
    cudaGetSymbolAddress((void**)&wq,  g_wq);
    cudaGetSymbolAddress((void**)&wk2, g_wk2);
    cudaGetSymbolAddress((void**)&gl,  g_gl);

    float* out = (float*)d_out;

    // weight packing
    pack3_kernel<<<(512 * 1536 / 4 + 255) / 256, 256>>>(a1_q, a1_k, a1_v, wq);
    pack2_kernel<<<(1024 * 1024 / 4 + 255) / 256, 256>>>(a2_k, a2_v, wk2);

    // 1. GroupNorm + transpose to tokens -> t
    groupnorm_kernel<<<BATCH * 32, 256>>>(in_q, gn_g, gn_b, t);

    // 2. x = t @ fc_in_w + fc_in_b
    gemm(t, 512, fc_in_w, 512, x, 512, nullptr, 0, fc_in_b, NTOK, 512, 512);

    // ---- self attention ----
    layernorm_kernel<<<NTOK / 8, 256>>>(x, ln2_g, ln2_b, t, NTOK);
    gemm(t, 512, wq, 1536, qkv, 1536, nullptr, 0, nullptr, NTOK, 1536, 512);
    {
        dim3 grid(8, 64);
        flash_self_kernel<<<grid, 256, FS_TOTAL * 4>>>(qkv, t);
    }
    gemm(t, 512, a1_o, 512, x, 512, x, 512, a1_ob, NTOK, 512, 512);

    // ---- cross attention ----
    layernorm_kernel<<<NTOK / 8, 256>>>(x, ln3_g, ln3_b, t, NTOK);
    gemm(t, 512, a2_q, 512, q, 512, nullptr, 0, nullptr, NTOK, 512, 512);
    gemm(in_kv, 1024, wk2, 1024, kv2, 1024, nullptr, 0, nullptr,
         BATCH * KVLEN, 1024, 1024);
    {
        dim3 grid(8, 64);
        flash_cross_kernel<<<grid, 256, CF_TOTAL * 4>>>(q, kv2, t);
    }
    gemm(t, 512, a2_o, 512, x, 512, x, 512, a2_ob, NTOK, 512, 512);

    // ---- feed-forward (GEGLU fused) ----
    layernorm_kernel<<<NTOK / 8, 256>>>(x, ln4_g, ln4_b, t, NTOK);
    gemm(t, 512, ff_proj_w, 4096, gl, 2048, nullptr, 0, ff_proj_b,
         NTOK, 2048, 512);
    gemm(t, 512, ff_proj_w + 2048, 4096, gl, 2048, gl, 2048,
         ff_proj_b + 2048, NTOK, 2048, 512, 1);
    gemm(gl, 2048, ff_out_w, 512, x, 512, x, 512, ff_out_b, NTOK, 512, 2048);

    // ---- output projection ----
    gemm(x, 512, fc_out_w, 512, t, 512, nullptr, 0, fc_out_b, NTOK, 512, 512);

    output_kernel<<<(BATCH * DIMC * SPATIAL) / 256, 256>>>(t, in_q, out);
}